// round 1
// baseline (speedup 1.0000x reference)
#include <cuda_runtime.h>
#include <math.h>

#define BB 2
#define PP 8192
#define KK 20
#define TILE 256

// Scratch (no allocation allowed): transformed db points/normals per side, accumulators.
__device__ double g_acc[2];
__device__ float g_xdb[2][BB * PP * 3];
__device__ float g_ndb[2][BB * PP * 3];

__global__ void init_kernel() {
    g_acc[0] = 0.0;
    g_acc[1] = 0.0;
}

__global__ void transform_kernel(const float* __restrict__ xyz1, const float* __restrict__ normal1,
                                 const float* __restrict__ xyz2, const float* __restrict__ normal2,
                                 const float* __restrict__ R12, const float* __restrict__ t12,
                                 const float* __restrict__ R21, const float* __restrict__ t21) {
    int i = blockIdx.x * blockDim.x + threadIdx.x;
    if (i >= BB * PP) return;
    int b = i >> 13;  // i / PP

    // side 0 db = R12 @ xyz2 + t12 ; normals R12 @ normal2
    {
        const float* R = R12 + b * 9;
        const float* t = t12 + b * 3;
        float x = xyz2[3 * i + 0], y = xyz2[3 * i + 1], z = xyz2[3 * i + 2];
        g_xdb[0][3 * i + 0] = R[0] * x + R[1] * y + R[2] * z + t[0];
        g_xdb[0][3 * i + 1] = R[3] * x + R[4] * y + R[5] * z + t[1];
        g_xdb[0][3 * i + 2] = R[6] * x + R[7] * y + R[8] * z + t[2];
        float nx = normal2[3 * i + 0], ny = normal2[3 * i + 1], nz = normal2[3 * i + 2];
        g_ndb[0][3 * i + 0] = R[0] * nx + R[1] * ny + R[2] * nz;
        g_ndb[0][3 * i + 1] = R[3] * nx + R[4] * ny + R[5] * nz;
        g_ndb[0][3 * i + 2] = R[6] * nx + R[7] * ny + R[8] * nz;
    }
    // side 1 db = R21 @ xyz1 + t21 ; normals R21 @ normal1
    {
        const float* R = R21 + b * 9;
        const float* t = t21 + b * 3;
        float x = xyz1[3 * i + 0], y = xyz1[3 * i + 1], z = xyz1[3 * i + 2];
        g_xdb[1][3 * i + 0] = R[0] * x + R[1] * y + R[2] * z + t[0];
        g_xdb[1][3 * i + 1] = R[3] * x + R[4] * y + R[5] * z + t[1];
        g_xdb[1][3 * i + 2] = R[6] * x + R[7] * y + R[8] * z + t[2];
        float nx = normal1[3 * i + 0], ny = normal1[3 * i + 1], nz = normal1[3 * i + 2];
        g_ndb[1][3 * i + 0] = R[0] * nx + R[1] * ny + R[2] * nz;
        g_ndb[1][3 * i + 1] = R[3] * nx + R[4] * ny + R[5] * nz;
        g_ndb[1][3 * i + 2] = R[6] * nx + R[7] * ny + R[8] * nz;
    }
}

// Main: thread per query. blockIdx.y = side. Queries of one block all belong to one batch
// (TILE=256 divides PP). Top-20 kept as sorted packed keys: high mantissa bits of d2 | 13-bit idx.
__global__ __launch_bounds__(TILE) void knn_kernel(
    const float* __restrict__ xyz1, const float* __restrict__ hsv1,
    const float* __restrict__ normal1, const float* __restrict__ nres1,
    const float* __restrict__ xyz2, const float* __restrict__ hsv2,
    const float* __restrict__ normal2, const float* __restrict__ nres2,
    const int* __restrict__ npts1, const int* __restrict__ npts2) {
    const int s = blockIdx.y;
    const int qi = blockIdx.x * TILE + threadIdx.x;  // 0 .. BB*PP-1
    const int b = qi >> 13;
    const int p = qi & (PP - 1);

    const float* xq   = s ? xyz2 : xyz1;
    const float* hq   = s ? hsv2 : hsv1;
    const float* nq   = s ? normal2 : normal1;
    const float* rq   = s ? nres2 : nres1;
    const float* hdb  = s ? hsv1 : hsv2;
    const float* rdb  = s ? nres1 : nres2;
    const int lq  = (s ? npts2 : npts1)[b];
    const int ldb = (s ? npts1 : npts2)[b];

    const float* xdb = &g_xdb[s][b * PP * 3];
    const float* ndb = &g_ndb[s][b * PP * 3];

    const float qx = xq[3 * qi + 0];
    const float qy = xq[3 * qi + 1];
    const float qz = xq[3 * qi + 2];

    float keys[KK];
#pragma unroll
    for (int k = 0; k < KK; k++) keys[k] = 3.0e38f;

    __shared__ float4 sm[TILE];

    const int ntile = (ldb + TILE - 1) / TILE;
    for (int tb = 0; tb < ntile; ++tb) {
        int j = tb * TILE + threadIdx.x;
        float4 v;
        if (j < ldb)
            v = make_float4(xdb[3 * j + 0], xdb[3 * j + 1], xdb[3 * j + 2], 0.f);
        else
            v = make_float4(1e30f, 1e30f, 1e30f, 0.f);
        __syncthreads();
        sm[threadIdx.x] = v;
        __syncthreads();

        const unsigned base = (unsigned)(tb * TILE);
#pragma unroll 8
        for (int jj = 0; jj < TILE; ++jj) {
            float4 pv = sm[jj];
            float dx = qx - pv.x;
            float dy = qy - pv.y;
            float dz = qz - pv.z;
            float d2 = fmaf(dx, dx, fmaf(dy, dy, dz * dz));
            if (d2 < keys[KK - 1]) {
                float kk = __uint_as_float((__float_as_uint(d2) & 0xFFFFE000u) | (base + jj));
#pragma unroll
                for (int k = 0; k < KK; k++) {
                    float lo = fminf(kk, keys[k]);
                    float hi = fmaxf(kk, keys[k]);
                    keys[k] = lo;
                    kk = hi;
                }
            }
        }
    }

    // Epilogue: recompute exact terms from recovered indices.
    float sum = 0.f;
    if (p < lq) {
        float ell = fmaxf(0.015f * (qz - 10.0f), 0.15f);
        float inv_ls = 1.0f / (ell * ell);
        float hx = hq[3 * qi + 0], hy = hq[3 * qi + 1], hz = hq[3 * qi + 2];
        float nx = nq[3 * qi + 0], ny = nq[3 * qi + 1], nz = nq[3 * qi + 2];
        float rqv = rq[qi];
#pragma unroll
        for (int k = 0; k < KK; k++) {
            int idx = (int)(__float_as_uint(keys[k]) & 0x1FFFu);
            // exact distance
            float px = xdb[3 * idx + 0], py = xdb[3 * idx + 1], pz = xdb[3 * idx + 2];
            float dx = qx - px, dy = qy - py, dz = qz - pz;
            float d2 = fmaf(dx, dx, fmaf(dy, dy, dz * dz));
            // color
            int g = b * PP + idx;
            float chx = hx - hdb[3 * g + 0];
            float chy = hy - hdb[3 * g + 1];
            float chz = hz - hdb[3 * g + 2];
            float cd = sqrtf(fmaf(chx, chx, fmaf(chy, chy, chz * chz)) + 1e-12f);
            // normal
            float ndot = fmaf(nx, ndb[3 * idx + 0], fmaf(ny, ndb[3 * idx + 1], nz * ndb[3 * idx + 2]));
            float rk = rdb[g];
            float alpha = 0.2f / (0.1f + rqv + rk);
            float nk = fmaxf(ndot * alpha, 0.0f);
            float e = expf(-(d2 * inv_ls + cd * 5.0f));
            sum += e * nk;
        }
    }

    // Block reduce + one double atomic per block.
    __shared__ float red[TILE];
    red[threadIdx.x] = sum;
    __syncthreads();
#pragma unroll
    for (int st = TILE / 2; st > 0; st >>= 1) {
        if (threadIdx.x < st) red[threadIdx.x] += red[threadIdx.x + st];
        __syncthreads();
    }
    if (threadIdx.x == 0) atomicAdd(&g_acc[s], (double)red[0]);
}

__global__ void finalize_kernel(const int* __restrict__ npts1, const int* __restrict__ npts2,
                                float* __restrict__ out) {
    double s1 = 0.0, s2 = 0.0;
    for (int b = 0; b < BB; b++) {
        s1 += (double)npts1[b];
        s2 += (double)npts2[b];
    }
    double k1 = g_acc[0] / (s1 * (double)KK);
    double k2 = g_acc[1] / (s2 * (double)KK);
    out[0] = (float)(0.5 * (k1 + k2));
}

extern "C" void kernel_launch(void* const* d_in, const int* in_sizes, int n_in,
                              void* d_out, int out_size) {
    const float* xyz1    = (const float*)d_in[0];
    const float* xyz2    = (const float*)d_in[1];
    const float* hsv1    = (const float*)d_in[2];
    const float* hsv2    = (const float*)d_in[3];
    const float* normal1 = (const float*)d_in[4];
    const float* normal2 = (const float*)d_in[5];
    const float* nres1   = (const float*)d_in[6];
    const float* nres2   = (const float*)d_in[7];
    const float* R12     = (const float*)d_in[8];
    const float* t12     = (const float*)d_in[9];
    const float* R21     = (const float*)d_in[10];
    const float* t21     = (const float*)d_in[11];
    const int*   npts1   = (const int*)d_in[12];
    const int*   npts2   = (const int*)d_in[13];
    float* out = (float*)d_out;

    init_kernel<<<1, 1>>>();
    transform_kernel<<<(BB * PP + 255) / 256, 256>>>(xyz1, normal1, xyz2, normal2,
                                                     R12, t12, R21, t21);
    dim3 grid(BB * PP / TILE, 2);
    knn_kernel<<<grid, TILE>>>(xyz1, hsv1, normal1, nres1,
                               xyz2, hsv2, normal2, nres2, npts1, npts2);
    finalize_kernel<<<1, 1>>>(npts1, npts2, out);
}